// round 4
// baseline (speedup 1.0000x reference)
#include <cuda_runtime.h>
#include <math.h>

#define TDIM   2048
#define BDIM   2
#define DMODEL 1024
#define NH     16
#define DH     64
#define WIN    128
#define MTOT   (BDIM*TDIM)          // 4096 rows

// -------- scratch (device globals: allocation-free) --------
__device__ float g_q [MTOT*DMODEL];
__device__ float g_k [MTOT*DMODEL];
__device__ float g_v [MTOT*DMODEL];
__device__ float g_ao[MTOT*DMODEL];
__device__ float g_cos[TDIM*32];
__device__ float g_sin[TDIM*32];

// ============================================================
// SGEMM: C[m][n] = sum_k A[m][k] * W[n][k]  (+bias), K=N=1024
// BM=BN=128, BK=8, 256 threads, 8x8 microtile, prefetched.
// ============================================================
template<bool HASBIAS>
__device__ __forceinline__ void sgemm_body(
    const float* __restrict__ A, const float* __restrict__ W,
    float* __restrict__ C, const float* __restrict__ bias)
{
    __shared__ float As[8][132];
    __shared__ float Bs[8][132];

    const int tid  = threadIdx.x;
    const int brow = blockIdx.y * 128;
    const int bcol = blockIdx.x * 128;

    const int lrow = tid >> 1;          // 0..127
    const int lk   = (tid & 1) * 4;     // 0 or 4

    const float* Ag = A + (brow + lrow) * DMODEL + lk;
    const float* Wg = W + (bcol + lrow) * DMODEL + lk;

    const int trow = (tid >> 4) * 8;    // 0..120
    const int tcol = (tid & 15) * 8;    // 0..120

    float acc[8][8];
    #pragma unroll
    for (int i = 0; i < 8; i++)
        #pragma unroll
        for (int j = 0; j < 8; j++) acc[i][j] = 0.0f;

    float4 a4 = *(const float4*)Ag;
    float4 b4 = *(const float4*)Wg;

    for (int k0 = 0; k0 < DMODEL; k0 += 8) {
        As[lk+0][lrow] = a4.x; As[lk+1][lrow] = a4.y;
        As[lk+2][lrow] = a4.z; As[lk+3][lrow] = a4.w;
        Bs[lk+0][lrow] = b4.x; Bs[lk+1][lrow] = b4.y;
        Bs[lk+2][lrow] = b4.z; Bs[lk+3][lrow] = b4.w;
        __syncthreads();

        if (k0 + 8 < DMODEL) {
            a4 = *(const float4*)(Ag + k0 + 8);
            b4 = *(const float4*)(Wg + k0 + 8);
        }

        #pragma unroll
        for (int kk = 0; kk < 8; kk++) {
            float4 x0 = *(const float4*)&As[kk][trow];
            float4 x1 = *(const float4*)&As[kk][trow + 4];
            float4 y0 = *(const float4*)&Bs[kk][tcol];
            float4 y1 = *(const float4*)&Bs[kk][tcol + 4];
            float ar[8] = {x0.x,x0.y,x0.z,x0.w,x1.x,x1.y,x1.z,x1.w};
            float br[8] = {y0.x,y0.y,y0.z,y0.w,y1.x,y1.y,y1.z,y1.w};
            #pragma unroll
            for (int i = 0; i < 8; i++)
                #pragma unroll
                for (int j = 0; j < 8; j++)
                    acc[i][j] = fmaf(ar[i], br[j], acc[i][j]);
        }
        __syncthreads();
    }

    float bv[8];
    if (HASBIAS) {
        #pragma unroll
        for (int j = 0; j < 8; j++) bv[j] = bias[bcol + tcol + j];
    }
    #pragma unroll
    for (int i = 0; i < 8; i++) {
        float* Cp = C + (brow + trow + i) * DMODEL + bcol + tcol;
        float4 v0 = make_float4(acc[i][0], acc[i][1], acc[i][2], acc[i][3]);
        float4 v1 = make_float4(acc[i][4], acc[i][5], acc[i][6], acc[i][7]);
        if (HASBIAS) {
            v0.x += bv[0]; v0.y += bv[1]; v0.z += bv[2]; v0.w += bv[3];
            v1.x += bv[4]; v1.y += bv[5]; v1.z += bv[6]; v1.w += bv[7];
        }
        *(float4*)Cp       = v0;
        *(float4*)(Cp + 4) = v1;
    }
}

extern "C" __global__ void __launch_bounds__(256, 2)
qkv_gemm_kernel(const float* __restrict__ X,
                const float* __restrict__ Wq,
                const float* __restrict__ Wk,
                const float* __restrict__ Wv)
{
    const float* W;
    float* C;
    if (blockIdx.z == 0)      { W = Wq; C = g_q; }
    else if (blockIdx.z == 1) { W = Wk; C = g_k; }
    else                      { W = Wv; C = g_v; }
    sgemm_body<false>(X, W, C, nullptr);
}

extern "C" __global__ void __launch_bounds__(256, 2)
out_gemm_kernel(const float* __restrict__ Wo,
                const float* __restrict__ bo,
                float* __restrict__ out)
{
    sgemm_body<true>(g_ao, Wo, out, bo);
}

// ============================================================
// RoPE: cos/sin table in double (phase accuracy), then apply.
// ============================================================
extern "C" __global__ void __launch_bounds__(256)
rope_table_kernel()
{
    int idx = blockIdx.x * 256 + threadIdx.x;   // < 2048*32
    int t = idx >> 5;
    int d = idx & 31;
    double freq = pow(10000.0, -(double)d / 32.0);
    double ang  = (double)t * freq;
    double sd, cd;
    sincos(ang, &sd, &cd);
    g_cos[idx] = (float)cd;
    g_sin[idx] = (float)sd;
}

extern "C" __global__ void __launch_bounds__(256)
rope_apply_kernel()
{
    int idx = blockIdx.x * 256 + threadIdx.x;   // < 4096*16*32
    int d  = idx & 31;
    int h  = (idx >> 5) & 15;
    int bt = idx >> 9;
    int t  = bt & (TDIM - 1);

    float c = g_cos[t * 32 + d];
    float s = g_sin[t * 32 + d];

    int base = bt * DMODEL + h * DH + d;

    float a = g_q[base], b = g_q[base + 32];
    g_q[base]      = a * c - b * s;
    g_q[base + 32] = b * c + a * s;

    a = g_k[base]; b = g_k[base + 32];
    g_k[base]      = a * c - b * s;
    g_k[base + 32] = b * c + a * s;
}

// ============================================================
// Sliding-window attention. 64-query tile, key window <=191.
// smem: Q[64][65] K[192][65] V[192][65] S[64][193]  (165888 B)
// ============================================================
#define ATTN_THREADS 512
#define ATTN_SMEM_FLOATS (64*65 + 192*65 + 192*65 + 64*193)
#define ATTN_SMEM_BYTES  (ATTN_SMEM_FLOATS * 4)

extern "C" __global__ void __launch_bounds__(ATTN_THREADS)
attn_kernel()
{
    extern __shared__ float sm[];
    float* Qs = sm;                    // [64][65]
    float* Ks = Qs + 64 * 65;          // [192][65]
    float* Vs = Ks + 192 * 65;         // [192][65]
    float* Ss = Vs + 192 * 65;         // [64][193]

    const int tid = threadIdx.x;
    const int q0  = blockIdx.x * 64;
    const int h   = blockIdx.y;
    const int b   = blockIdx.z;

    const int k0 = max(0, q0 - (WIN - 1));
    const int nk = q0 + 64 - k0;       // <= 191

    const float* Qg = g_q + (b * TDIM + q0) * DMODEL + h * DH;
    const float* Kg = g_k + (b * TDIM + k0) * DMODEL + h * DH;
    const float* Vg = g_v + (b * TDIM + k0) * DMODEL + h * DH;

    for (int idx = tid; idx < 64 * 64; idx += ATTN_THREADS) {
        int i = idx >> 6, d = idx & 63;
        Qs[i * 65 + d] = Qg[i * DMODEL + d];
    }
    for (int idx = tid; idx < nk * 64; idx += ATTN_THREADS) {
        int j = idx >> 6, d = idx & 63;
        Ks[j * 65 + d] = Kg[j * DMODEL + d];
        Vs[j * 65 + d] = Vg[j * DMODEL + d];
    }
    __syncthreads();

    // scores + mask
    for (int idx = tid; idx < 64 * 192; idx += ATTN_THREADS) {
        int i = idx / 192;
        int j = idx - i * 192;
        int iq = q0 + i;
        int jg = k0 + j;
        float sv = -INFINITY;
        if (j < nk && jg <= iq && jg >= iq - (WIN - 1)) {
            const float* qp = Qs + i * 65;
            const float* kp = Ks + j * 65;
            float a0 = 0.f, a1 = 0.f, a2 = 0.f, a3 = 0.f;
            #pragma unroll
            for (int d = 0; d < 64; d += 4) {
                a0 = fmaf(qp[d],     kp[d],     a0);
                a1 = fmaf(qp[d + 1], kp[d + 1], a1);
                a2 = fmaf(qp[d + 2], kp[d + 2], a2);
                a3 = fmaf(qp[d + 3], kp[d + 3], a3);
            }
            sv = ((a0 + a1) + (a2 + a3)) * 0.125f;   // 1/sqrt(64)
        }
        Ss[i * 193 + j] = sv;
    }
    __syncthreads();

    // softmax per row (row j=i always valid -> max finite)
    if (tid < 64) {
        float* sp = Ss + tid * 193;
        float m = -INFINITY;
        for (int j = 0; j < 192; j++) m = fmaxf(m, sp[j]);
        float sum = 0.f;
        for (int j = 0; j < 192; j++) {
            float e = __expf(sp[j] - m);
            sp[j] = e;
            sum += e;
        }
        float inv = 1.0f / sum;
        for (int j = 0; j < 192; j++) sp[j] *= inv;
    }
    __syncthreads();

    // O = P @ V, restricted to the valid window per row
    float* Og = g_ao + (b * TDIM + q0) * DMODEL + h * DH;
    for (int idx = tid; idx < 64 * 64; idx += ATTN_THREADS) {
        int i = idx >> 6, d = idx & 63;
        int iq  = q0 + i;
        int jlo = max(0, iq - (WIN - 1)) - k0;
        int jhi = iq - k0;
        const float* sp = Ss + i * 193;
        const float* vp = Vs + d;
        float a0 = 0.f, a1 = 0.f;
        int j = jlo;
        for (; j + 1 <= jhi; j += 2) {
            a0 = fmaf(sp[j],     vp[j * 65],       a0);
            a1 = fmaf(sp[j + 1], vp[(j + 1) * 65], a1);
        }
        if (j <= jhi) a0 = fmaf(sp[j], vp[j * 65], a0);
        Og[i * DMODEL + d] = a0 + a1;
    }
}

// ============================================================
// launch
// ============================================================
extern "C" void kernel_launch(void* const* d_in, const int* in_sizes, int n_in,
                              void* d_out, int out_size)
{
    const float* X  = (const float*)d_in[0];
    const float* Wq = (const float*)d_in[1];
    const float* Wk = (const float*)d_in[2];
    const float* Wv = (const float*)d_in[3];
    const float* Wo = (const float*)d_in[4];
    const float* bo = (const float*)d_in[5];
    float* out = (float*)d_out;

    cudaFuncSetAttribute(attn_kernel,
                         cudaFuncAttributeMaxDynamicSharedMemorySize,
                         ATTN_SMEM_BYTES);

    rope_table_kernel<<<(TDIM * 32) / 256, 256>>>();                 // 65536 angles
    qkv_gemm_kernel<<<dim3(DMODEL / 128, MTOT / 128, 3), 256>>>(X, Wq, Wk, Wv);
    rope_apply_kernel<<<(MTOT * NH * 32) / 256, 256>>>();
    attn_kernel<<<dim3(TDIM / 64, NH, BDIM), ATTN_THREADS, ATTN_SMEM_BYTES>>>();
    out_gemm_kernel<<<dim3(DMODEL / 128, MTOT / 128, 1), 256>>>(Wo, bo, out);
}